// round 1
// baseline (speedup 1.0000x reference)
#include <cuda_runtime.h>
#include <math.h>

// Problem constants
#define B_SZ     512
#define LEAVES   256
#define HIDDEN   300
#define WORD_DIM 300
#define REL      3
#define M0       (B_SZ * 2 * LEAVES)   // 262144 leaf rows

// GEMM tiling
#define BM 128
#define BN 64
#define BK 8
#define TM 8
#define TN 4
// threads = (BM/TM)*(BN/TN) = 16*16 = 256

// Scratch (device globals — allocation-free per harness rules)
__device__ __align__(16) float g_bufA[(size_t)M0 * HIDDEN];        // 314.6 MB
__device__ __align__(16) float g_bufB[(size_t)(M0 / 2) * HIDDEN];  // 157.3 MB
__device__ __align__(16) float g_WtLeaf[WORD_DIM * HIDDEN];        // [K=300][N=300]
__device__ __align__(16) float g_WtH[2 * HIDDEN * HIDDEN];         // [K=600][N=300]

// ---------------------------------------------------------------------------
// Transpose W[N][K] -> Wt[K][N] (tiny, once per launch)
// ---------------------------------------------------------------------------
__global__ void transpose_kernel(const float* __restrict__ W, float* __restrict__ Wt,
                                 int N, int K) {
    int idx = blockIdx.x * blockDim.x + threadIdx.x;
    if (idx < N * K) {
        int n = idx / K;
        int k = idx % K;
        Wt[(size_t)k * N + n] = W[idx];
    }
}

// ---------------------------------------------------------------------------
// Tiled SGEMM: C[M,N] = A[M,K] @ Wt[K,N] (+ bias)
// GATHER: A row m = embedding[ids[m]] (row length K)
// ---------------------------------------------------------------------------
template <bool GATHER, bool BIAS>
__global__ __launch_bounds__(256)
void gemm_kernel(const float* __restrict__ A, const int* __restrict__ ids,
                 const float* __restrict__ Wt, const float* __restrict__ bias,
                 float* __restrict__ C, int M, int N, int K) {
    __shared__ float As[BK][BM];
    __shared__ float Bs[BK][BN];

    const int tid = threadIdx.x;
    const int m0 = blockIdx.y * BM;
    const int n0 = blockIdx.x * BN;
    const int ty = tid >> 4;      // 0..15 (row group)
    const int tx = tid & 15;      // 0..15 (col group)

    // A-tile load mapping: 2 threads per row, 4 consecutive k's each
    const int a_row = tid >> 1;          // 0..127
    const int a_kc  = (tid & 1) * 4;     // 0 or 4
    const int srcRow = m0 + a_row;
    const bool rowValid = srcRow < M;

    const float* arow_ptr;
    if (GATHER) {
        int g = rowValid ? ids[srcRow] : 0;
        arow_ptr = A + (size_t)g * K;
    } else {
        arow_ptr = A + (size_t)(rowValid ? srcRow : 0) * K;
    }

    // B-tile load mapping: 2 consecutive n's per thread
    const int b_idx = tid * 2;
    const int bk = b_idx >> 6;   // 0..7
    const int bn = b_idx & 63;   // 0..62 even

    float acc[TM][TN];
#pragma unroll
    for (int i = 0; i < TM; i++)
#pragma unroll
        for (int j = 0; j < TN; j++) acc[i][j] = 0.f;

    for (int kk = 0; kk < K; kk += BK) {
        // --- load A tile ---
        if (rowValid && kk + BK <= K) {
            float4 v = *reinterpret_cast<const float4*>(arow_ptr + kk + a_kc);
            As[a_kc + 0][a_row] = v.x;
            As[a_kc + 1][a_row] = v.y;
            As[a_kc + 2][a_row] = v.z;
            As[a_kc + 3][a_row] = v.w;
        } else {
#pragma unroll
            for (int c = 0; c < 4; c++) {
                int k = kk + a_kc + c;
                As[a_kc + c][a_row] = (rowValid && k < K) ? arow_ptr[k] : 0.f;
            }
        }
        // --- load B tile ---
#pragma unroll
        for (int c = 0; c < 2; c++) {
            int k = kk + bk;
            int n = n0 + bn + c;
            Bs[bk][bn + c] = (k < K && n < N) ? Wt[(size_t)k * N + n] : 0.f;
        }
        __syncthreads();

        // --- microkernel ---
#pragma unroll
        for (int k = 0; k < BK; k++) {
            float a[TM], b[TN];
#pragma unroll
            for (int i = 0; i < TM; i++) a[i] = As[k][ty * TM + i];
#pragma unroll
            for (int j = 0; j < TN; j++) b[j] = Bs[k][tx * TN + j];
#pragma unroll
            for (int i = 0; i < TM; i++)
#pragma unroll
                for (int j = 0; j < TN; j++) acc[i][j] += a[i] * b[j];
        }
        __syncthreads();
    }

    // --- epilogue ---
#pragma unroll
    for (int i = 0; i < TM; i++) {
        int m = m0 + ty * TM + i;
        if (m >= M) continue;
#pragma unroll
        for (int j = 0; j < TN; j++) {
            int n = n0 + tx * TN + j;
            if (n < N) {
                float v = acc[i][j];
                if (BIAS) v += bias[n];
                C[(size_t)m * N + n] = v;
            }
        }
    }
}

// ---------------------------------------------------------------------------
// Classifier: per-batch sigmoid(600) -> 3 dots -> log_softmax
// roots layout: [512*2, 300] contiguous => [512, 600]
// ---------------------------------------------------------------------------
__global__ void classifier_kernel(const float* __restrict__ roots,
                                  const float* __restrict__ Wc,
                                  const float* __restrict__ bc,
                                  float* __restrict__ out) {
    const int b = blockIdx.x;
    const float* f = roots + (size_t)b * (2 * HIDDEN);

    float p0 = 0.f, p1 = 0.f, p2 = 0.f;
    for (int j = threadIdx.x; j < 2 * HIDDEN; j += blockDim.x) {
        float v = 1.f / (1.f + expf(-f[j]));
        p0 += v * Wc[j];
        p1 += v * Wc[2 * HIDDEN + j];
        p2 += v * Wc[4 * HIDDEN + j];
    }
#pragma unroll
    for (int o = 16; o; o >>= 1) {
        p0 += __shfl_down_sync(0xffffffffu, p0, o);
        p1 += __shfl_down_sync(0xffffffffu, p1, o);
        p2 += __shfl_down_sync(0xffffffffu, p2, o);
    }
    __shared__ float red[3][4];
    int warp = threadIdx.x >> 5, lane = threadIdx.x & 31;
    if (lane == 0) { red[0][warp] = p0; red[1][warp] = p1; red[2][warp] = p2; }
    __syncthreads();
    if (threadIdx.x == 0) {
        float l0 = bc[0], l1 = bc[1], l2 = bc[2];
        int nw = blockDim.x >> 5;
        for (int w = 0; w < nw; w++) { l0 += red[0][w]; l1 += red[1][w]; l2 += red[2][w]; }
        float m = fmaxf(l0, fmaxf(l1, l2));
        float s = expf(l0 - m) + expf(l1 - m) + expf(l2 - m);
        float lse = m + logf(s);
        out[b * 3 + 0] = l0 - lse;
        out[b * 3 + 1] = l1 - lse;
        out[b * 3 + 2] = l2 - lse;
    }
}

// ---------------------------------------------------------------------------
// kernel_launch
// inputs: 0 word_ids(int32) 1 embedding 2 W_leaf 3 W_h 4 b_h 5 W_cls 6 b_cls
// ---------------------------------------------------------------------------
extern "C" void kernel_launch(void* const* d_in, const int* in_sizes, int n_in,
                              void* d_out, int out_size) {
    const int*   word_ids  = (const int*)d_in[0];
    const float* embedding = (const float*)d_in[1];
    const float* W_leaf    = (const float*)d_in[2];
    const float* W_h       = (const float*)d_in[3];
    const float* b_h       = (const float*)d_in[4];
    const float* W_cls     = (const float*)d_in[5];
    const float* b_cls     = (const float*)d_in[6];
    float* out = (float*)d_out;

    float *bufA, *bufB, *wtl, *wth;
    cudaGetSymbolAddress((void**)&bufA, g_bufA);
    cudaGetSymbolAddress((void**)&bufB, g_bufB);
    cudaGetSymbolAddress((void**)&wtl, g_WtLeaf);
    cudaGetSymbolAddress((void**)&wth, g_WtH);

    // Stage transposed weights (coalesced B-tile loads)
    transpose_kernel<<<(HIDDEN * WORD_DIM + 255) / 256, 256>>>(W_leaf, wtl, HIDDEN, WORD_DIM);
    transpose_kernel<<<(HIDDEN * 2 * HIDDEN + 255) / 256, 256>>>(W_h, wth, HIDDEN, 2 * HIDDEN);

    // Leaf: H0[262144, 300] = emb[ids] @ W_leaf^T
    {
        dim3 grid((HIDDEN + BN - 1) / BN, (M0 + BM - 1) / BM);
        gemm_kernel<true, false><<<grid, 256>>>(embedding, word_ids, wtl, nullptr,
                                                bufA, M0, HIDDEN, WORD_DIM);
    }

    // Tree levels: view input [M, 300] as [M/2, 600]; out[M/2, 300]
    float* cur = bufA;
    int M = M0;
    for (int l = 0; l < 8; l++) {
        M >>= 1;
        float* nxt = (cur == bufA) ? bufB : bufA;
        dim3 grid((HIDDEN + BN - 1) / BN, (M + BM - 1) / BM);
        gemm_kernel<false, true><<<grid, 256>>>(cur, nullptr, wth, b_h,
                                                nxt, M, HIDDEN, 2 * HIDDEN);
        cur = nxt;
    }
    // cur now holds roots [1024, 300] == [512, 600]

    classifier_kernel<<<B_SZ, 128>>>(cur, W_cls, b_cls, out);
    (void)in_sizes; (void)n_in; (void)out_size;
}

// round 2
// speedup vs baseline: 3.5022x; 3.5022x over previous
#include <cuda_runtime.h>
#include <math.h>
#include <stdint.h>

// ---------------- problem constants ----------------
#define B_SZ    512
#define LEAVES  256
#define HIDDEN  300
#define VOCAB   50000
#define P       320                  // padded feature pitch
#define M0      (B_SZ * 2 * LEAVES)  // 262144 leaf rows
#define KP_LEAF 320
#define KP_H    640

// ---------------- GEMM tiling ----------------
#define BM 64
#define BK 16
#define WN 40   // cols per warp (8 warps * 40 = 320)

// ---------------- device scratch (no allocation allowed) ----------------
__device__ __align__(16) float g_bufA[(size_t)M0 * P];          // 335 MB
__device__ __align__(16) float g_bufB[(size_t)(M0 / 2) * P];    // 167 MB
__device__ __align__(16) float g_embT[(size_t)VOCAB * HIDDEN];  // tf32-rounded embedding
__device__ __align__(16) float g_Bleaf[KP_LEAF * P];            // packed leaf weights
__device__ __align__(16) float g_Bh[KP_H * P];                  // packed tree weights
__device__ __align__(16) float g_bias[P];                       // padded b_h

// ---------------- helpers ----------------
__device__ __forceinline__ float tf32r(float x) {
    float y;
    asm("cvt.rna.tf32.f32 %0, %1;" : "=f"(y) : "f"(x));
    return y;
}
__device__ __forceinline__ uint32_t s2u(const void* p) {
    uint32_t a;
    asm("{.reg .u64 t; cvta.to.shared.u64 t, %1; cvt.u32.u64 %0, t;}" : "=r"(a) : "l"(p));
    return a;
}
__device__ __forceinline__ void cpa16(uint32_t dst, const void* src, int srcBytes) {
    asm volatile("cp.async.cg.shared.global [%0], [%1], 16, %2;\n"
                 :: "r"(dst), "l"(src), "r"(srcBytes));
}
__device__ __forceinline__ void cpa_commit() { asm volatile("cp.async.commit_group;\n"); }
__device__ __forceinline__ void cpa_wait1()  { asm volatile("cp.async.wait_group 1;\n"); }

__device__ __forceinline__ void mma_tf32(float* d, const uint32_t* a, uint32_t b0, uint32_t b1) {
    asm volatile(
        "mma.sync.aligned.m16n8k8.row.col.f32.tf32.tf32.f32 "
        "{%0,%1,%2,%3}, {%4,%5,%6,%7}, {%8,%9}, {%0,%1,%2,%3};"
        : "+f"(d[0]), "+f"(d[1]), "+f"(d[2]), "+f"(d[3])
        : "r"(a[0]), "r"(a[1]), "r"(a[2]), "r"(a[3]), "r"(b0), "r"(b1));
}

// ---------------- prep kernels ----------------
__global__ void prep_emb(const float* __restrict__ e, float* __restrict__ o, int n) {
    int i = blockIdx.x * blockDim.x + threadIdx.x;
    if (i < n) o[i] = tf32r(e[i]);
}

// Pack weights into per-panel smem layout:
// offset(k, n) = (k>>4)*16*P + (((k>>2)&3)*P + n)*4 + (k&3)
__device__ __forceinline__ size_t packoff(int k, int n) {
    return (size_t)(k >> 4) * (16 * P) + (size_t)(((k >> 2) & 3) * P + n) * 4 + (k & 3);
}

__global__ void prep_Bleaf(const float* __restrict__ W) {  // W_leaf[300][300], row n col k
    int idx = blockIdx.x * blockDim.x + threadIdx.x;
    if (idx >= KP_LEAF * P) return;
    int k = idx / P, n = idx % P;
    float v = (k < HIDDEN && n < HIDDEN) ? tf32r(W[n * HIDDEN + k]) : 0.f;
    g_Bleaf[packoff(k, n)] = v;
}

__global__ void prep_Bh(const float* __restrict__ W) {  // W_h[300][600], row n col k
    int idx = blockIdx.x * blockDim.x + threadIdx.x;
    if (idx >= KP_H * P) return;
    int k = idx / P, n = idx % P;
    int half = (k >= P) ? 1 : 0;
    int k2 = k - half * P;
    float v = (k2 < HIDDEN && n < HIDDEN) ? tf32r(W[n * (2 * HIDDEN) + half * HIDDEN + k2]) : 0.f;
    g_Bh[packoff(k, n)] = v;
}

__global__ void prep_bias(const float* __restrict__ b) {
    int n = threadIdx.x;
    if (n < P) g_bias[n] = (n < HIDDEN) ? b[n] : 0.f;
}

// ---------------- main tf32 tensor-core GEMM ----------------
// C[M, P(=320)] = A[M, Kp] @ Bg + bias, A rows either gathered (leaf) or contiguous.
// Grid: M/64 CTAs, 256 threads (8 warps, each owns 64 x 40).
template <bool GATHER, bool BIAS>
__global__ __launch_bounds__(256, 2)
void gemm_tf32(const float* __restrict__ A, const int* __restrict__ ids,
               const float* __restrict__ Bg, const float* __restrict__ bias,
               float* __restrict__ C, int Kp) {
    // As: [kg 0..3][m 0..63][c 0..3]  (1024 floats / buffer)
    // Bs: [kg 0..3][n 0..319][c 0..3] (5120 floats / buffer)
    __shared__ float As[2][BK * BM];
    __shared__ float Bs[2][BK * P];

    const int t  = threadIdx.x;
    const int m0 = blockIdx.x * BM;
    const int lr = t >> 2;    // row this thread loads (0..63)
    const int lg = t & 3;     // k-chunk (0..3)

    const float* arow;
    if (GATHER) arow = A + (size_t)ids[m0 + lr] * HIDDEN;
    else        arow = A + (size_t)(m0 + lr) * Kp;

    const uint32_t asA = s2u(As);
    const uint32_t asB = s2u(Bs);

    const int wid  = t >> 5;
    const int lane = t & 31;
    const int wn   = wid * WN;       // warp col base
    const int r    = lane >> 2;      // 0..7
    const int cql  = lane & 3;       // 0..3

    float acc[4][5][4];
#pragma unroll
    for (int mt = 0; mt < 4; mt++)
#pragma unroll
        for (int nt = 0; nt < 5; nt++)
#pragma unroll
            for (int q = 0; q < 4; q++) acc[mt][nt][q] = 0.f;

    const int KT = Kp / BK;

    // ---- tile loaders ----
    auto loadA = [&](int buf, int kk) {
        int kc = kk + lg * 4;
        uint32_t dst = asA + (uint32_t)(buf * (BK * BM) + lg * 256 + lr * 4) * 4;
        int sz = 16;
        if (GATHER && kc >= HIDDEN) sz = 0;  // zero-fill pad K
        cpa16(dst, arow + kc, sz);
    };
    auto loadB = [&](int buf, int kt) {
        const char* src = (const char*)(Bg + (size_t)kt * (BK * P));
        uint32_t dst = asB + (uint32_t)(buf * (BK * P)) * 4;
#pragma unroll
        for (int i = 0; i < 5; i++) {
            int e = (t + i * 256) * 16;
            cpa16(dst + e, src + e, 16);
        }
    };

    loadA(0, 0);
    loadB(0, 0);
    cpa_commit();

    for (int kt = 0; kt < KT; kt++) {
        int buf = kt & 1;
        if (kt + 1 < KT) {
            loadA(buf ^ 1, (kt + 1) * BK);
            loadB(buf ^ 1, kt + 1);
        }
        cpa_commit();
        cpa_wait1();
        __syncthreads();

        const float* as = As[buf];
        const float* bs = Bs[buf];
#pragma unroll
        for (int s = 0; s < 2; s++) {
            uint32_t a[4][4];
#pragma unroll
            for (int mt = 0; mt < 4; mt++) {
                int m = mt * 16 + r;
                a[mt][0] = __float_as_uint(as[(2 * s)     * 256 + m       * 4 + cql]);
                a[mt][1] = __float_as_uint(as[(2 * s)     * 256 + (m + 8) * 4 + cql]);
                a[mt][2] = __float_as_uint(as[(2 * s + 1) * 256 + m       * 4 + cql]);
                a[mt][3] = __float_as_uint(as[(2 * s + 1) * 256 + (m + 8) * 4 + cql]);
            }
#pragma unroll
            for (int nt = 0; nt < 5; nt++) {
                int n = wn + nt * 8 + r;
                uint32_t b0 = __float_as_uint(bs[(2 * s)     * 1280 + n * 4 + cql]);
                uint32_t b1 = __float_as_uint(bs[(2 * s + 1) * 1280 + n * 4 + cql]);
#pragma unroll
                for (int mt = 0; mt < 4; mt++) mma_tf32(acc[mt][nt], a[mt], b0, b1);
            }
        }
        __syncthreads();
    }

    // ---- epilogue: bias + tf32 round + store ----
#pragma unroll
    for (int mt = 0; mt < 4; mt++) {
#pragma unroll
        for (int nt = 0; nt < 5; nt++) {
            int col = wn + nt * 8 + cql * 2;
            int row = m0 + mt * 16 + r;
            float v0 = acc[mt][nt][0], v1 = acc[mt][nt][1];
            float v2 = acc[mt][nt][2], v3 = acc[mt][nt][3];
            if (BIAS) {
                float bb0 = __ldg(bias + col), bb1 = __ldg(bias + col + 1);
                v0 += bb0; v1 += bb1; v2 += bb0; v3 += bb1;
            }
            float2 o0 = make_float2(tf32r(v0), tf32r(v1));
            float2 o1 = make_float2(tf32r(v2), tf32r(v3));
            *reinterpret_cast<float2*>(&C[(size_t)row * P + col])       = o0;
            *reinterpret_cast<float2*>(&C[(size_t)(row + 8) * P + col]) = o1;
        }
    }
}

// ---------------- classifier: sigmoid -> 3 dots -> log_softmax ----------------
// roots: [1024][320]; sample b feature j: j<300 -> row 2b col j ; j>=300 -> row 2b+1 col j-300
__global__ void classifier_kernel(const float* __restrict__ roots,
                                  const float* __restrict__ Wc,
                                  const float* __restrict__ bc,
                                  float* __restrict__ out) {
    const int b = blockIdx.x;
    const float* base = roots + (size_t)(2 * b) * P;

    float p0 = 0.f, p1 = 0.f, p2 = 0.f;
    for (int j = threadIdx.x; j < 2 * HIDDEN; j += blockDim.x) {
        int off = (j < HIDDEN) ? j : (j + (P - HIDDEN));  // j or j+20
        float v = 1.f / (1.f + expf(-base[off]));
        p0 += v * Wc[j];
        p1 += v * Wc[2 * HIDDEN + j];
        p2 += v * Wc[4 * HIDDEN + j];
    }
#pragma unroll
    for (int o = 16; o; o >>= 1) {
        p0 += __shfl_down_sync(0xffffffffu, p0, o);
        p1 += __shfl_down_sync(0xffffffffu, p1, o);
        p2 += __shfl_down_sync(0xffffffffu, p2, o);
    }
    __shared__ float red[3][4];
    int warp = threadIdx.x >> 5, lane = threadIdx.x & 31;
    if (lane == 0) { red[0][warp] = p0; red[1][warp] = p1; red[2][warp] = p2; }
    __syncthreads();
    if (threadIdx.x == 0) {
        float l0 = bc[0], l1 = bc[1], l2 = bc[2];
        int nw = blockDim.x >> 5;
        for (int w = 0; w < nw; w++) { l0 += red[0][w]; l1 += red[1][w]; l2 += red[2][w]; }
        float m = fmaxf(l0, fmaxf(l1, l2));
        float s = expf(l0 - m) + expf(l1 - m) + expf(l2 - m);
        float lse = m + logf(s);
        out[b * 3 + 0] = l0 - lse;
        out[b * 3 + 1] = l1 - lse;
        out[b * 3 + 2] = l2 - lse;
    }
}

// ---------------- kernel_launch ----------------
// inputs: 0 word_ids(int32) 1 embedding 2 W_leaf 3 W_h 4 b_h 5 W_cls 6 b_cls
extern "C" void kernel_launch(void* const* d_in, const int* in_sizes, int n_in,
                              void* d_out, int out_size) {
    const int*   word_ids  = (const int*)d_in[0];
    const float* embedding = (const float*)d_in[1];
    const float* W_leaf    = (const float*)d_in[2];
    const float* W_h       = (const float*)d_in[3];
    const float* b_h       = (const float*)d_in[4];
    const float* W_cls     = (const float*)d_in[5];
    const float* b_cls     = (const float*)d_in[6];
    float* out = (float*)d_out;

    float *bufA, *bufB, *embT, *bleaf, *bh, *bias;
    cudaGetSymbolAddress((void**)&bufA, g_bufA);
    cudaGetSymbolAddress((void**)&bufB, g_bufB);
    cudaGetSymbolAddress((void**)&embT, g_embT);
    cudaGetSymbolAddress((void**)&bleaf, g_Bleaf);
    cudaGetSymbolAddress((void**)&bh, g_Bh);
    cudaGetSymbolAddress((void**)&bias, g_bias);

    // prep: round embedding to tf32, pack weights into panel layout
    {
        int n = VOCAB * HIDDEN;
        prep_emb<<<(n + 255) / 256, 256>>>(embedding, embT, n);
        prep_Bleaf<<<(KP_LEAF * P + 255) / 256, 256>>>(W_leaf);
        prep_Bh<<<(KP_H * P + 255) / 256, 256>>>(W_h);
        prep_bias<<<1, P>>>(b_h);
    }

    // leaf: H0[262144, 320] = tf32(emb[ids]) @ Bleaf
    gemm_tf32<true, false><<<M0 / BM, 256>>>(embT, word_ids, bleaf, nullptr, bufA, KP_LEAF);

    // tree: view [M*2, 320] as [M, 640]
    float* cur = bufA;
    int M = M0;
    for (int l = 0; l < 8; l++) {
        M >>= 1;
        float* nxt = (cur == bufA) ? bufB : bufA;
        gemm_tf32<false, true><<<M / BM, 256>>>(cur, nullptr, bh, bias, nxt, KP_H);
        cur = nxt;
    }

    classifier_kernel<<<B_SZ, 128>>>(cur, W_cls, b_cls, out);
    (void)in_sizes; (void)n_in; (void)out_size;
}

// round 4
// speedup vs baseline: 5.5381x; 1.5813x over previous
#include <cuda_runtime.h>
#include <cuda_fp16.h>
#include <math.h>
#include <stdint.h>

// ---------------- problem constants ----------------
#define B_SZ    512
#define LEAVES  256
#define HIDDEN  300
#define VOCAB   50000
#define P       320                  // padded feature pitch (fp16 elements)
#define EPITCH  304                  // embedding fp16 pitch (608B, 16B-aligned)
#define M0      (B_SZ * 2 * LEAVES)  // 262144 leaf rows
#define KP_LEAF 320
#define KP_H    640

// ---------------- GEMM tiling ----------------
#define BM     64
#define BK     16        // K per chunk (fp16) -> one m16n8k16 step
#define NSTAGE 4
#define APITCH 12        // half2 (u32) per A/B row in smem (8 used + 4 pad)
#define ATILE_U32 (BM * APITCH)      // 768 u32 = 3072 B
#define BTILE_U32 (P * APITCH)       // 3840 u32 = 15360 B
#define STAGE_A_B (ATILE_U32 * 4)    // bytes
#define STAGE_B_B (BTILE_U32 * 4)
#define OFF_B_BASE (NSTAGE * STAGE_A_B)
#define SMEM_TOT (NSTAGE * (STAGE_A_B + STAGE_B_B))   // 4*18432 = 73728 B

// ---------------- device scratch ----------------
__device__ __align__(16) __half g_bufA[(size_t)M0 * P];          // 167 MB
__device__ __align__(16) __half g_bufB[(size_t)(M0 / 2) * P];    // 84 MB
__device__ __align__(16) __half g_embH[(size_t)VOCAB * EPITCH];  // 30.4 MB
__device__ __align__(16) uint32_t g_BleafP[(KP_LEAF / BK) * BTILE_U32];  // 20 chunks
__device__ __align__(16) uint32_t g_BhP[(KP_H / BK) * BTILE_U32];        // 40 chunks
__device__ __align__(16) float g_bias[P];

// ---------------- PTX helpers ----------------
__device__ __forceinline__ uint32_t s2u(const void* p) {
    uint32_t a;
    asm("{.reg .u64 t; cvta.to.shared.u64 t, %1; cvt.u32.u64 %0, t;}" : "=r"(a) : "l"(p));
    return a;
}
__device__ __forceinline__ void cpa16(uint32_t dst, const void* src, int srcBytes) {
    asm volatile("cp.async.cg.shared.global [%0], [%1], 16, %2;\n"
                 :: "r"(dst), "l"(src), "r"(srcBytes));
}
__device__ __forceinline__ void cpa_commit() { asm volatile("cp.async.commit_group;\n"); }
template <int N> __device__ __forceinline__ void cpa_wait() {
    asm volatile("cp.async.wait_group %0;\n" :: "n"(N));
}
__device__ __forceinline__ void mma_f16(float* d, const uint32_t* a, uint32_t b0, uint32_t b1) {
    asm volatile(
        "mma.sync.aligned.m16n8k16.row.col.f32.f16.f16.f32 "
        "{%0,%1,%2,%3}, {%4,%5,%6,%7}, {%8,%9}, {%0,%1,%2,%3};"
        : "+f"(d[0]), "+f"(d[1]), "+f"(d[2]), "+f"(d[3])
        : "r"(a[0]), "r"(a[1]), "r"(a[2]), "r"(a[3]), "r"(b0), "r"(b1));
}

// ---------------- prep kernels ----------------
__global__ void prep_embH(const float* __restrict__ e, __half* __restrict__ o, int n) {
    int i = blockIdx.x * blockDim.x + threadIdx.x;
    if (i >= n) return;
    int row = i / EPITCH, col = i % EPITCH;
    o[i] = __float2half_rn(col < HIDDEN ? e[row * HIDDEN + col] : 0.f);
}
// Packed B image: [chunk][n(320)][APITCH u32], entry k2 (0..7 used) = halves {k, k+1}
__global__ void pack_leaf(const float* __restrict__ W, uint32_t* __restrict__ dst, int total) {
    int e = blockIdx.x * blockDim.x + threadIdx.x;
    if (e >= total) return;
    int kt = e / BTILE_U32, rme = e % BTILE_U32;
    int n = rme / APITCH, k2 = rme % APITCH;
    float v0 = 0.f, v1 = 0.f;
    if (k2 < 8) {
        int k = kt * BK + 2 * k2;
        if (n < HIDDEN && k < HIDDEN)     v0 = W[n * HIDDEN + k];
        if (n < HIDDEN && k + 1 < HIDDEN) v1 = W[n * HIDDEN + k + 1];
    }
    __half2 h = __floats2half2_rn(v0, v1);
    dst[e] = *reinterpret_cast<uint32_t*>(&h);
}
__global__ void pack_tree(const float* __restrict__ W, uint32_t* __restrict__ dst, int total) {
    int e = blockIdx.x * blockDim.x + threadIdx.x;
    if (e >= total) return;
    int kt = e / BTILE_U32, rme = e % BTILE_U32;
    int n = rme / APITCH, k2 = rme % APITCH;
    float v0 = 0.f, v1 = 0.f;
    if (k2 < 8) {
        int kg = kt * BK + 2 * k2;
        int half = (kg >= P) ? 1 : 0;
        int kk = kg - half * P;
        if (n < HIDDEN && kk < HIDDEN)     v0 = W[n * (2 * HIDDEN) + half * HIDDEN + kk];
        if (n < HIDDEN && kk + 1 < HIDDEN) v1 = W[n * (2 * HIDDEN) + half * HIDDEN + kk + 1];
    }
    __half2 h = __floats2half2_rn(v0, v1);
    dst[e] = *reinterpret_cast<uint32_t*>(&h);
}
__global__ void prep_bias(const float* __restrict__ b) {
    int n = threadIdx.x;
    if (n < P) g_bias[n] = (n < HIDDEN) ? b[n] : 0.f;
}

// ---------------- fp16 mma.sync GEMM ----------------
// C[M, 320](fp16) = A[M, Kp](fp16) @ Bpacked + bias.  grid.x = M/64, 256 thr (8 warps x 64x40)
template <bool GATHER, bool BIAS>
__global__ __launch_bounds__(256)
void gemm_f16(const __half* __restrict__ A, const int* __restrict__ ids,
              const uint32_t* __restrict__ Bp, const float* __restrict__ bias,
              __half* __restrict__ C, int Kp) {
    extern __shared__ uint32_t smem[];
    const uint32_t sb = s2u(smem);
    const int t = threadIdx.x;
    const int wid = t >> 5, lane = t & 31;
    const int m0 = blockIdx.x * BM;
    const int KT = Kp / BK;

    // A loader mapping: threads 0..127, row m = t>>1, granule g = t&1 (8 halves each)
    const int lm = t >> 1, lg = t & 1;
    const __half* arow = nullptr;
    if (t < 128) {
        if (GATHER) arow = A + (size_t)ids[m0 + lm] * EPITCH;
        else        arow = A + (size_t)(m0 + lm) * Kp;
    }

    auto loadA = [&](int s, int kt) {
        if (t < 128) {
            int kstart = kt * BK + lg * 8;
            uint32_t dst = sb + s * STAGE_A_B + (lm * APITCH + lg * 4) * 4;
            int sz = 16;
            if (GATHER) sz = (kstart + 8 <= EPITCH) ? 16 : 0;
            cpa16(dst, arow + kstart, sz);
        }
    };
    auto loadB = [&](int s, int kt) {
        const uint32_t* src = Bp + (size_t)kt * BTILE_U32;
        uint32_t dst = sb + OFF_B_BASE + s * STAGE_B_B;
#pragma unroll
        for (int i = 0; i < 4; i++) {
            int idx = t + i * 256;
            if (idx < BTILE_U32 / 4) cpa16(dst + idx * 16, src + idx * 4, 16);
        }
    };

    // fragment indices
    const int r = lane >> 2;     // 0..7
    const int c = lane & 3;      // 0..3
    const int wn = wid * 40;     // warp col base

    float acc[4][5][4];
#pragma unroll
    for (int mt = 0; mt < 4; mt++)
#pragma unroll
        for (int nt = 0; nt < 5; nt++)
#pragma unroll
            for (int q = 0; q < 4; q++) acc[mt][nt][q] = 0.f;

    // prologue: fill 3 stages
    loadA(0, 0); loadB(0, 0); cpa_commit();
    loadA(1, 1); loadB(1, 1); cpa_commit();
    loadA(2, 2); loadB(2, 2); cpa_commit();

    for (int kt = 0; kt < KT; kt++) {
        const int s = kt & 3;
        // issue refill for chunk kt+3 into stage (kt+3)&3
        if (kt + 3 < KT) { loadA((kt + 3) & 3, kt + 3); loadB((kt + 3) & 3, kt + 3); }
        cpa_commit();
        cpa_wait<3>();          // chunk kt landed
        __syncthreads();

        const uint32_t* as = smem + s * ATILE_U32;
        const uint32_t* bs = smem + NSTAGE * ATILE_U32 + s * BTILE_U32;

        uint32_t a[4][4];
#pragma unroll
        for (int mt = 0; mt < 4; mt++) {
            int m = mt * 16 + r;
            a[mt][0] = as[m * APITCH + c];
            a[mt][1] = as[(m + 8) * APITCH + c];
            a[mt][2] = as[m * APITCH + c + 4];
            a[mt][3] = as[(m + 8) * APITCH + c + 4];
        }
#pragma unroll
        for (int nt = 0; nt < 5; nt++) {
            int n = wn + nt * 8 + r;
            uint32_t b0 = bs[n * APITCH + c];
            uint32_t b1 = bs[n * APITCH + c + 4];
#pragma unroll
            for (int mt = 0; mt < 4; mt++) mma_f16(acc[mt][nt], a[mt], b0, b1);
        }
        __syncthreads();
    }

    // epilogue: bias + fp16 round + half2 stores
#pragma unroll
    for (int mt = 0; mt < 4; mt++) {
        int row = m0 + mt * 16 + r;
#pragma unroll
        for (int nt = 0; nt < 5; nt++) {
            int col = wn + nt * 8 + 2 * c;
            float v0 = acc[mt][nt][0], v1 = acc[mt][nt][1];
            float v2 = acc[mt][nt][2], v3 = acc[mt][nt][3];
            if (BIAS) {
                float b0 = __ldg(bias + col), b1 = __ldg(bias + col + 1);
                v0 += b0; v1 += b1; v2 += b0; v3 += b1;
            }
            __half2 h0 = __floats2half2_rn(v0, v1);
            __half2 h1 = __floats2half2_rn(v2, v3);
            *reinterpret_cast<__half2*>(&C[(size_t)row * P + col])       = h0;
            *reinterpret_cast<__half2*>(&C[(size_t)(row + 8) * P + col]) = h1;
        }
    }
}

// ---------------- classifier ----------------
__global__ void classifier_kernel(const __half* __restrict__ roots,
                                  const float* __restrict__ Wc,
                                  const float* __restrict__ bc,
                                  float* __restrict__ out) {
    const int b = blockIdx.x;
    const __half* base = roots + (size_t)(2 * b) * P;
    float p0 = 0.f, p1 = 0.f, p2 = 0.f;
    for (int j = threadIdx.x; j < 2 * HIDDEN; j += blockDim.x) {
        int off = (j < HIDDEN) ? j : (j + (P - HIDDEN));
        float v = 1.f / (1.f + expf(-__half2float(base[off])));
        p0 += v * Wc[j];
        p1 += v * Wc[2 * HIDDEN + j];
        p2 += v * Wc[4 * HIDDEN + j];
    }
#pragma unroll
    for (int o = 16; o; o >>= 1) {
        p0 += __shfl_down_sync(0xffffffffu, p0, o);
        p1 += __shfl_down_sync(0xffffffffu, p1, o);
        p2 += __shfl_down_sync(0xffffffffu, p2, o);
    }
    __shared__ float red[3][4];
    int warp = threadIdx.x >> 5, lane = threadIdx.x & 31;
    if (lane == 0) { red[0][warp] = p0; red[1][warp] = p1; red[2][warp] = p2; }
    __syncthreads();
    if (threadIdx.x == 0) {
        float l0 = bc[0], l1 = bc[1], l2 = bc[2];
        int nw = blockDim.x >> 5;
        for (int w = 0; w < nw; w++) { l0 += red[0][w]; l1 += red[1][w]; l2 += red[2][w]; }
        float m = fmaxf(l0, fmaxf(l1, l2));
        float s = expf(l0 - m) + expf(l1 - m) + expf(l2 - m);
        float lse = m + logf(s);
        out[b * 3 + 0] = l0 - lse;
        out[b * 3 + 1] = l1 - lse;
        out[b * 3 + 2] = l2 - lse;
    }
}

// ---------------- kernel_launch ----------------
// inputs: 0 word_ids(int32) 1 embedding 2 W_leaf 3 W_h 4 b_h 5 W_cls 6 b_cls
extern "C" void kernel_launch(void* const* d_in, const int* in_sizes, int n_in,
                              void* d_out, int out_size) {
    const int*   word_ids  = (const int*)d_in[0];
    const float* embedding = (const float*)d_in[1];
    const float* W_leaf    = (const float*)d_in[2];
    const float* W_h       = (const float*)d_in[3];
    const float* b_h       = (const float*)d_in[4];
    const float* W_cls     = (const float*)d_in[5];
    const float* b_cls     = (const float*)d_in[6];
    float* out = (float*)d_out;

    __half *bufA, *bufB, *embH;
    uint32_t *bleaf, *bh;
    float *bias;
    cudaGetSymbolAddress((void**)&bufA, g_bufA);
    cudaGetSymbolAddress((void**)&bufB, g_bufB);
    cudaGetSymbolAddress((void**)&embH, g_embH);
    cudaGetSymbolAddress((void**)&bleaf, g_BleafP);
    cudaGetSymbolAddress((void**)&bh, g_BhP);
    cudaGetSymbolAddress((void**)&bias, g_bias);

    static bool attr_done = false;
    if (!attr_done) {
        cudaFuncSetAttribute(gemm_f16<true, false>,
                             cudaFuncAttributeMaxDynamicSharedMemorySize, SMEM_TOT);
        cudaFuncSetAttribute(gemm_f16<false, true>,
                             cudaFuncAttributeMaxDynamicSharedMemorySize, SMEM_TOT);
        attr_done = true;
    }

    {
        int n = VOCAB * EPITCH;
        prep_embH<<<(n + 255) / 256, 256>>>(embedding, embH, n);
        int tl = (KP_LEAF / BK) * BTILE_U32;
        pack_leaf<<<(tl + 255) / 256, 256>>>(W_leaf, bleaf, tl);
        int tt = (KP_H / BK) * BTILE_U32;
        pack_tree<<<(tt + 255) / 256, 256>>>(W_h, bh, tt);
        prep_bias<<<1, P>>>(b_h);
    }

    // leaf: H0[262144, 320] = fp16(emb[ids]) @ Bleaf
    gemm_f16<true, false><<<M0 / BM, 256, SMEM_TOT>>>(embH, word_ids, bleaf, nullptr, bufA, KP_LEAF);

    // tree levels: view [2M, 320] as [M, 640]
    __half* cur = bufA;
    int M = M0;
    for (int l = 0; l < 8; l++) {
        M >>= 1;
        __half* nxt = (cur == bufA) ? bufB : bufA;
        gemm_f16<false, true><<<M / BM, 256, SMEM_TOT>>>(cur, nullptr, bh, bias, nxt, KP_H);
        cur = nxt;
    }

    classifier_kernel<<<B_SZ, 128>>>(cur, W_cls, b_cls, out);
    (void)in_sizes; (void)n_in; (void)out_size;
}